// round 1
// baseline (speedup 1.0000x reference)
#include <cuda_runtime.h>
#include <math.h>

#define N_NODES 20000
#define N_EDGES 320000

// ---------------- scratch (device globals: no allocation allowed) ----------------
__device__ float g_sv[N_NODES * 256];    // per node: s[64], then v[u][i] at 64+3u+i
__device__ float g_agg[N_NODES * 512];   // per node: s_agg[128] (A|D), v_agg at 128+3w+i (w<64:B, w>=64:C)
__device__ float g_gate[N_NODES * 64];   // silu_n(s_h[64:128])

__device__ __forceinline__ float silu_n(float x) {
    // silu(x) * 1.679177
    return 1.679177f * x * (1.0f / (1.0f + __expf(-x)));
}

// ---------------- K1: lin1 (s and v), one block per node ----------------
__global__ void k1_lin1(const float* __restrict__ ns, const float* __restrict__ nv,
                        const float* __restrict__ W1s, const float* __restrict__ W1v) {
    int n = blockIdx.x;
    int w = threadIdx.x;  // 0..63
    __shared__ float sns[64];
    __shared__ float snv[192];
    sns[w] = ns[(size_t)n * 64 + w];
#pragma unroll
    for (int j = 0; j < 3; j++) snv[w + 64 * j] = nv[(size_t)n * 192 + w + 64 * j];
    __syncthreads();
    float as = 0.f, a0 = 0.f, a1 = 0.f, a2 = 0.f;
#pragma unroll 4
    for (int u = 0; u < 64; u++) {
        float ws = W1s[u * 64 + w];
        float wv = W1v[u * 64 + w];
        as += sns[u] * ws;
        a0 += snv[u * 3 + 0] * wv;
        a1 += snv[u * 3 + 1] * wv;
        a2 += snv[u * 3 + 2] * wv;
    }
    const float s8 = 0.125f;  // 1/sqrt(64)
    float* o = g_sv + (size_t)n * 256;
    o[w] = as * s8;
    o[64 + 3 * w + 0] = a0 * s8;
    o[64 + 3 * w + 1] = a1 * s8;
    o[64 + 3 * w + 2] = a2 * s8;
}

// ---------------- K2: zero the aggregation buffer ----------------
__global__ void k2_zero() {
    int i = blockIdx.x * blockDim.x + threadIdx.x;
    int stride = gridDim.x * blockDim.x;
    float4* p = (float4*)g_agg;
    const int n4 = N_NODES * 512 / 4;
    for (; i < n4; i += stride) p[i] = make_float4(0.f, 0.f, 0.f, 0.f);
}

// ---------------- K3: fused edge MLP + gather + scatter (warp per edge) ----------------
// dyn smem: W0[512] W1[4096] W2[16384] h[8*64] wout[8*256] = 23552 floats = 94208 B
__global__ void k3_edge(const float* __restrict__ esh, const float* __restrict__ emb,
                        const int* __restrict__ esrc, const int* __restrict__ edst,
                        const float* __restrict__ W0, const float* __restrict__ W1,
                        const float* __restrict__ W2) {
    extern __shared__ float sm[];
    float* sW0 = sm;             // 512
    float* sW1 = sW0 + 512;      // 4096
    float* sW2 = sW1 + 4096;     // 16384
    float* sH = sW2 + 16384;     // 8 warps * 64
    float* sWo = sH + 512;       // 8 warps * 256
    int tid = threadIdx.x;
    for (int i = tid; i < 512; i += 256) sW0[i] = W0[i];
    for (int i = tid; i < 4096; i += 256) sW1[i] = W1[i];
    for (int i = tid; i < 16384; i += 256) sW2[i] = W2[i];
    __syncthreads();

    int warp = tid >> 5, lane = tid & 31;
    float* shh = sH + warp * 64;
    float* shw = sWo + warp * 256;
    const float inv_sqrt3 = 0.57735026918962576f;
    const int ntile = N_EDGES / 8;  // 40000 exactly

    for (int tile = blockIdx.x; tile < ntile; tile += gridDim.x) {
        int e = tile * 8 + warp;
        int src = __ldg(esrc + e);
        int dst = __ldg(edst + e);
        // defensive clamp (no-op when input ordering is as assumed)
        src = min(max(src, 0), N_NODES - 1);
        dst = min(max(dst, 0), N_NODES - 1);
        float y0 = __ldg(esh + (size_t)e * 4 + 0);
        float Y1 = __ldg(esh + (size_t)e * 4 + 1);
        float Y2 = __ldg(esh + (size_t)e * 4 + 2);
        float Y3 = __ldg(esh + (size_t)e * 4 + 3);
        float eb[8];
#pragma unroll
        for (int b = 0; b < 8; b++) eb[b] = __ldg(emb + (size_t)e * 8 + b);

        // fc0: each lane computes 2 of 64 hidden units
#pragma unroll
        for (int half = 0; half < 2; half++) {
            int j = lane + 32 * half;
            float a = 0.f;
#pragma unroll
            for (int b = 0; b < 8; b++) a += eb[b] * sW0[b * 64 + j];
            shh[j] = silu_n(a * 0.35355339059327373f);  // 1/sqrt(8)
        }
        __syncwarp();

        // fc1
        float h2a = 0.f, h2b = 0.f;
#pragma unroll 4
        for (int k = 0; k < 64; k++) {
            float hk = shh[k];
            h2a += hk * sW1[k * 64 + lane];
            h2b += hk * sW1[k * 64 + lane + 32];
        }
        h2a = silu_n(h2a * 0.125f);
        h2b = silu_n(h2b * 0.125f);
        __syncwarp();
        shh[lane] = h2a;
        shh[lane + 32] = h2b;
        __syncwarp();

        // fc2: lane owns outputs 8*lane .. 8*lane+7
        float acc[8];
#pragma unroll
        for (int r = 0; r < 8; r++) acc[r] = 0.f;
#pragma unroll 4
        for (int k = 0; k < 64; k++) {
            float hk = shh[k];
            const float4* row = (const float4*)(sW2 + k * 256 + 8 * lane);
            float4 wlo = row[0], whi = row[1];
            acc[0] += hk * wlo.x; acc[1] += hk * wlo.y;
            acc[2] += hk * wlo.z; acc[3] += hk * wlo.w;
            acc[4] += hk * whi.x; acc[5] += hk * whi.y;
            acc[6] += hk * whi.z; acc[7] += hk * whi.w;
        }
        float4* wo = (float4*)(shw + 8 * lane);
        wo[0] = make_float4(acc[0] * 0.125f, acc[1] * 0.125f, acc[2] * 0.125f, acc[3] * 0.125f);
        wo[1] = make_float4(acc[4] * 0.125f, acc[5] * 0.125f, acc[6] * 0.125f, acc[7] * 0.125f);
        __syncwarp();

        // gather src row + coalesced atomic scatter to dst row; 1/16 folded into K4
        const float* svrow = g_sv + (size_t)src * 256;
        float* aggrow = g_agg + (size_t)dst * 512;
#pragma unroll
        for (int half = 0; half < 2; half++) {
            int u = lane + 32 * half;
            float wA = shw[u], wB = shw[64 + u], wC = shw[128 + u], wD = shw[192 + u];
            float sA = __ldg(svrow + u);
            float v0 = __ldg(svrow + 64 + 3 * u + 0);
            float v1 = __ldg(svrow + 64 + 3 * u + 1);
            float v2 = __ldg(svrow + 64 + 3 * u + 2);
            atomicAdd(aggrow + u, wA * sA * y0);
            atomicAdd(aggrow + 64 + u, wD * (v0 * Y1 + v1 * Y2 + v2 * Y3) * inv_sqrt3);
            float bs = wB * sA;
            atomicAdd(aggrow + 128 + 3 * u + 0, bs * Y1);
            atomicAdd(aggrow + 128 + 3 * u + 1, bs * Y2);
            atomicAdd(aggrow + 128 + 3 * u + 2, bs * Y3);
            float cy = wC * y0;
            atomicAdd(aggrow + 320 + 3 * u + 0, cy * v0);
            atomicAdd(aggrow + 320 + 3 * u + 1, cy * v1);
            atomicAdd(aggrow + 320 + 3 * u + 2, cy * v2);
        }
        __syncwarp();
    }
}

// ---------------- K4a: s_h = [agg_s | ns(x)attr] @ Wcat, gates + out_s ----------------
// dyn smem: Wcat 384*128 + ops 384*8 = 52224 floats = 208896 B
__global__ void k4a(const float* __restrict__ ns, const float* __restrict__ attr,
                    const float* __restrict__ Wl2s, const float* __restrict__ Wscs,
                    float* __restrict__ out) {
    extern __shared__ float sm[];
    float* sW = sm;            // [384][128]
    float* sOp = sW + 49152;   // [384][8]
    int tid = threadIdx.x;
    const float lin2n = 0.08838834764831845f;  // 1/sqrt(128)
    const float scn = 0.0625f;                 // 1/sqrt(256)
    for (int i = tid; i < 16384; i += 256) sW[i] = Wl2s[i] * lin2n;
    for (int i = tid; i < 32768; i += 256) sW[16384 + i] = Wscs[i] * scn;
    __syncthreads();

    int w = tid & 127, nh = tid >> 7;
    const int ntile = N_NODES / 8;  // 2500

    for (int tile = blockIdx.x; tile < ntile; tile += gridDim.x) {
        int n0 = tile * 8;
        {
            int k = tid & 127, nd = tid >> 7;
#pragma unroll
            for (int nn = 0; nn < 4; nn++) {
                int node = nd + nn * 2;
                sOp[k * 8 + node] = g_agg[(size_t)(n0 + node) * 512 + k] * 0.0625f;  // /N_NEIGH
            }
            int m = tid;  // 0..255 = (u,v)
            int u = m >> 2, v = m & 3;
#pragma unroll
            for (int node = 0; node < 8; node++) {
                sOp[(128 + m) * 8 + node] =
                    ns[(size_t)(n0 + node) * 64 + u] * attr[(size_t)(n0 + node) * 4 + v];
            }
        }
        __syncthreads();

        float a0 = 0.f, a1 = 0.f, a2 = 0.f, a3 = 0.f;
#pragma unroll 4
        for (int k = 0; k < 384; k++) {
            float wk = sW[k * 128 + w];
            float4 op = *(const float4*)(sOp + k * 8 + nh * 4);
            a0 += wk * op.x; a1 += wk * op.y; a2 += wk * op.z; a3 += wk * op.w;
        }
        float r[4] = {a0, a1, a2, a3};
#pragma unroll
        for (int j = 0; j < 4; j++) {
            int n = n0 + nh * 4 + j;
            float val = silu_n(r[j]);
            if (w < 64) out[(size_t)n * 256 + w] = val;
            else        g_gate[(size_t)n * 64 + (w - 64)] = val;
        }
        __syncthreads();
    }
}

// ---------------- K4b: v_h = [agg_v | nv(x)attr] @ Wvcat, gate multiply + out_v ----------------
// dyn smem: Wvcat 384*64 + ops 384*4*4 = 30720 floats = 122880 B
__global__ void k4b(const float* __restrict__ nv, const float* __restrict__ attr,
                    const float* __restrict__ Wl2v, const float* __restrict__ Wscv,
                    float* __restrict__ out) {
    extern __shared__ float sm[];
    float* sW = sm;            // [384][64]
    float* sOp = sW + 24576;   // [384][4 nodes][4 (xyz+pad)]
    int tid = threadIdx.x;
    const float lin2n = 0.08838834764831845f;
    const float scn = 0.0625f;
    for (int i = tid; i < 8192; i += 256) sW[i] = Wl2v[i] * lin2n;
    for (int i = tid; i < 16384; i += 256) sW[8192 + i] = Wscv[i] * scn;
    __syncthreads();

    int w = tid & 63, node = tid >> 6;
    const int ntile = N_NODES / 4;  // 5000

    for (int tile = blockIdx.x; tile < ntile; tile += gridDim.x) {
        int n0 = tile * 4;
        for (int idx = tid; idx < 1536; idx += 256) {
            int k = idx >> 2, nd = idx & 3;
            int n = n0 + nd;
            float o0, o1, o2;
            if (k < 128) {
                const float* p = g_agg + (size_t)n * 512 + 128 + k * 3;
                o0 = p[0] * 0.0625f; o1 = p[1] * 0.0625f; o2 = p[2] * 0.0625f;
            } else {
                int m = k - 128;
                int u = m >> 2, v = m & 3;
                float av = attr[(size_t)n * 4 + v];
                const float* p = nv + (size_t)n * 192 + u * 3;
                o0 = p[0] * av; o1 = p[1] * av; o2 = p[2] * av;
            }
            *(float4*)(sOp + idx * 4) = make_float4(o0, o1, o2, 0.f);
        }
        __syncthreads();

        float a0 = 0.f, a1 = 0.f, a2 = 0.f;
#pragma unroll 4
        for (int k = 0; k < 384; k++) {
            float wk = sW[k * 64 + w];
            float4 op = *(const float4*)(sOp + (k * 4 + node) * 4);
            a0 += wk * op.x; a1 += wk * op.y; a2 += wk * op.z;
        }
        int n = n0 + node;
        float gate = g_gate[(size_t)n * 64 + w];
        float* o = out + (size_t)n * 256 + 64 + 3 * w;
        o[0] = gate * a0; o[1] = gate * a1; o[2] = gate * a2;
        __syncthreads();
    }
}

// ---------------- launch ----------------
extern "C" void kernel_launch(void* const* d_in, const int* in_sizes, int n_in,
                              void* d_out, int out_size) {
    const float* node_scalars  = (const float*)d_in[0];
    const float* node_vectors  = (const float*)d_in[1];
    const float* node_attr     = (const float*)d_in[2];
    const float* edge_sh       = (const float*)d_in[3];
    const float* edge_embedded = (const float*)d_in[4];
    const int*   edge_src      = (const int*)d_in[5];
    const int*   edge_dst      = (const int*)d_in[6];
    const float* W_lin1_s      = (const float*)d_in[7];
    const float* W_lin1_v      = (const float*)d_in[8];
    const float* W_fc0         = (const float*)d_in[9];
    const float* W_fc1         = (const float*)d_in[10];
    const float* W_fc2         = (const float*)d_in[11];
    const float* W_lin2_s      = (const float*)d_in[12];
    const float* W_lin2_v      = (const float*)d_in[13];
    const float* W_sc_s        = (const float*)d_in[14];
    const float* W_sc_v        = (const float*)d_in[15];
    float* out = (float*)d_out;

    cudaFuncSetAttribute(k3_edge, cudaFuncAttributeMaxDynamicSharedMemorySize, 94208);
    cudaFuncSetAttribute(k4a, cudaFuncAttributeMaxDynamicSharedMemorySize, 208896);
    cudaFuncSetAttribute(k4b, cudaFuncAttributeMaxDynamicSharedMemorySize, 122880);

    k1_lin1<<<N_NODES, 64>>>(node_scalars, node_vectors, W_lin1_s, W_lin1_v);
    k2_zero<<<1024, 256>>>();
    k3_edge<<<296, 256, 94208>>>(edge_sh, edge_embedded, edge_src, edge_dst,
                                 W_fc0, W_fc1, W_fc2);
    k4a<<<148, 256, 208896>>>(node_scalars, node_attr, W_lin2_s, W_sc_s, out);
    k4b<<<148, 256, 122880>>>(node_vectors, node_attr, W_lin2_v, W_sc_v, out);
}

// round 5
// speedup vs baseline: 2.4247x; 2.4247x over previous
#include <cuda_runtime.h>
#include <math.h>

#define N_NODES 20000
#define N_EDGES 320000

// ---------------- scratch (device globals) ----------------
// g_sv per node: s[0:64], v planar: 64 + 64*i + u   (i=0..2)
__device__ float g_sv[N_NODES * 256];
// g_agg per node: A[0:64], D[64:128], B planes 128+64*i+u, C planes 320+64*i+u
__device__ float g_agg[N_NODES * 512];
__device__ float g_gate[N_NODES * 64];

__device__ __forceinline__ float silu_n(float x) {
    return 1.679177f * x * (1.0f / (1.0f + __expf(-x)));
}

// ---------------- f32x2 packed-FMA helpers (Blackwell FFMA2) ----------------
typedef unsigned long long u64t;
__device__ __forceinline__ u64t pk2(float lo, float hi) {
    u64t r; asm("mov.b64 %0, {%1, %2};" : "=l"(r) : "f"(lo), "f"(hi)); return r;
}
__device__ __forceinline__ u64t pkdup(float v) {
    u64t r; asm("mov.b64 %0, {%1, %1};" : "=l"(r) : "f"(v)); return r;
}
__device__ __forceinline__ void fma2(u64t& d, u64t a, u64t b) {
    asm("fma.rn.f32x2 %0, %1, %2, %0;" : "+l"(d) : "l"(a), "l"(b));
}
__device__ __forceinline__ float2 up2(u64t v) {
    float2 r; asm("mov.b64 {%0, %1}, %2;" : "=f"(r.x), "=f"(r.y) : "l"(v)); return r;
}

// ---------------- K1: lin1 (s and v), one node per 64 threads ----------------
__global__ void k1_lin1(const float* __restrict__ ns, const float* __restrict__ nv,
                        const float* __restrict__ W1s, const float* __restrict__ W1v) {
    int n = blockIdx.x;
    int w = threadIdx.x;  // 0..63
    __shared__ float sns[64];
    __shared__ float snv[192];
    sns[w] = ns[(size_t)n * 64 + w];
#pragma unroll
    for (int j = 0; j < 3; j++) snv[w + 64 * j] = nv[(size_t)n * 192 + w + 64 * j];
    __syncthreads();
    float as = 0.f, a0 = 0.f, a1 = 0.f, a2 = 0.f;
#pragma unroll 4
    for (int u = 0; u < 64; u++) {
        float ws = W1s[u * 64 + w];
        float wv = W1v[u * 64 + w];
        as += sns[u] * ws;
        a0 += snv[u * 3 + 0] * wv;
        a1 += snv[u * 3 + 1] * wv;
        a2 += snv[u * 3 + 2] * wv;
    }
    const float s8 = 0.125f;  // 1/sqrt(64)
    float* o = g_sv + (size_t)n * 256;
    o[w] = as * s8;
    o[64 + w] = a0 * s8;
    o[128 + w] = a1 * s8;
    o[192 + w] = a2 * s8;
}

// ---------------- K2: zero the aggregation buffer ----------------
__global__ void k2_zero() {
    int i = blockIdx.x * blockDim.x + threadIdx.x;
    int stride = gridDim.x * blockDim.x;
    float4* p = (float4*)g_agg;
    const int n4 = N_NODES * 512 / 4;
    for (; i < n4; i += stride) p[i] = make_float4(0.f, 0.f, 0.f, 0.f);
}

// ---------------- K3: fused edge MLP + scatter; each WARP processes its own 8 edges ----------------
// smem: W0 512 + W1 4096 + W2 16384 + 8 warps * 688 = 26496 floats = 105984 B
#define K3_SMEM 105984
__global__ void __launch_bounds__(256, 2)
k3_edge(const float* __restrict__ esh, const float* __restrict__ emb,
        const int* __restrict__ esrc, const int* __restrict__ edst,
        const float* __restrict__ W0, const float* __restrict__ W1,
        const float* __restrict__ W2) {
    extern __shared__ float sm[];
    float* sW0 = sm;            // 512   (pre-scaled 1/sqrt8)
    float* sW1 = sW0 + 512;     // 4096  (pre-scaled 0.125)
    float* sW2 = sW1 + 4096;    // 16384 (pre-scaled 0.125)
    int tid = threadIdx.x;
    for (int i = tid; i < 512; i += 256)   sW0[i] = W0[i] * 0.35355339059327373f;
    for (int i = tid; i < 4096; i += 256)  sW1[i] = W1[i] * 0.125f;
    for (int i = tid; i < 16384; i += 256) sW2[i] = W2[i] * 0.125f;
    __syncthreads();

    int warp = tid >> 5, lane = tid & 31;
    float* pH  = sm + 20992 + warp * 688;  // [64][stride 9] h buffer
    float* pEB = pH + 576;                 // 64: emb for 8 edges
    float* pSH = pEB + 64;                 // 32: sh for 8 edges
    int*   pIX = (int*)(pSH + 32);         // 16: src[8], dst[8]

    const float inv_sqrt3 = 0.57735026918962576f;
    const int ntile = N_EDGES / 8;  // 40000

    // distribute tiles per-WARP, not per-block
    int gw = blockIdx.x * 8 + warp;
    int gstride = gridDim.x * 8;

    for (int tile = gw; tile < ntile; tile += gstride) {
        int e0 = tile * 8;
        // ---- load edge meta (coalesced) ----
        if (lane < 16) pIX[lane] = (lane < 8) ? __ldg(esrc + e0 + lane)
                                              : __ldg(edst + e0 + lane - 8);
        pEB[lane]      = __ldg(emb + (size_t)e0 * 8 + lane);
        pEB[lane + 32] = __ldg(emb + (size_t)e0 * 8 + 32 + lane);
        pSH[lane]      = __ldg(esh + (size_t)e0 * 4 + lane);
        __syncwarp();

        // ---- fc0: h0[j][e], lane computes j=lane, lane+32 ----
#pragma unroll
        for (int e = 0; e < 8; e++) {
            float eb[8];
#pragma unroll
            for (int b = 0; b < 8; b++) eb[b] = pEB[e * 8 + b];
#pragma unroll
            for (int jj = 0; jj < 2; jj++) {
                int j = lane + 32 * jj;
                float a = 0.f;
#pragma unroll
                for (int b = 0; b < 8; b++) a += eb[b] * sW0[b * 64 + j];
                pH[j * 9 + e] = silu_n(a);
            }
        }
        __syncwarp();

        // ---- fc1: h1[k1][e] for k1 = lane, lane+32 (FFMA2 over edge pairs) ----
        u64t h1[2][4] = {{0ull,0ull,0ull,0ull},{0ull,0ull,0ull,0ull}};
#pragma unroll 4
        for (int k = 0; k < 64; k++) {
            u64t wd0 = pkdup(sW1[k * 64 + lane]);
            u64t wd1 = pkdup(sW1[k * 64 + lane + 32]);
#pragma unroll
            for (int ep = 0; ep < 4; ep++) {
                u64t hp = pk2(pH[k * 9 + 2 * ep], pH[k * 9 + 2 * ep + 1]);
                fma2(h1[0][ep], wd0, hp);
                fma2(h1[1][ep], wd1, hp);
            }
        }
        __syncwarp();
#pragma unroll
        for (int kk = 0; kk < 2; kk++)
#pragma unroll
            for (int ep = 0; ep < 4; ep++) {
                float2 v = up2(h1[kk][ep]);
                pH[(lane + 32 * kk) * 9 + 2 * ep]     = silu_n(v.x);
                pH[(lane + 32 * kk) * 9 + 2 * ep + 1] = silu_n(v.y);
            }
        __syncwarp();

        // ---- fc2: lane owns cols lane+32c (c=0..7); acc[c][edge-pair] ----
        u64t acc[8][4];
#pragma unroll
        for (int c = 0; c < 8; c++)
#pragma unroll
            for (int ep = 0; ep < 4; ep++) acc[c][ep] = 0ull;
#pragma unroll 2
        for (int k = 0; k < 64; k++) {
            u64t wd[8];
#pragma unroll
            for (int c = 0; c < 8; c++) wd[c] = pkdup(sW2[k * 256 + lane + 32 * c]);
#pragma unroll
            for (int ep = 0; ep < 4; ep++) {
                u64t hp = pk2(pH[k * 9 + 2 * ep], pH[k * 9 + 2 * ep + 1]);
#pragma unroll
                for (int c = 0; c < 8; c++) fma2(acc[c][ep], wd[c], hp);
            }
        }
        __syncwarp();

        // ---- epilogue: per edge gather + coalesced atomic scatter ----
#pragma unroll
        for (int e = 0; e < 8; e++) {
            int src = pIX[e], dst = pIX[8 + e];
            src = min(max(src, 0), N_NODES - 1);
            dst = min(max(dst, 0), N_NODES - 1);
            float y0 = pSH[4 * e + 0], Y1 = pSH[4 * e + 1];
            float Y2 = pSH[4 * e + 2], Y3 = pSH[4 * e + 3];
            const float* sv = g_sv + (size_t)src * 256;
            float* ag = g_agg + (size_t)dst * 512;
#pragma unroll
            for (int half = 0; half < 2; half++) {
                int u = lane + 32 * half;
                float2 tA = up2(acc[half][e >> 1]);
                float2 tB = up2(acc[half + 2][e >> 1]);
                float2 tC = up2(acc[half + 4][e >> 1]);
                float2 tD = up2(acc[half + 6][e >> 1]);
                float wA = (e & 1) ? tA.y : tA.x;
                float wB = (e & 1) ? tB.y : tB.x;
                float wC = (e & 1) ? tC.y : tC.x;
                float wD = (e & 1) ? tD.y : tD.x;
                float sA = __ldg(sv + u);
                float v0 = __ldg(sv + 64 + u);
                float v1 = __ldg(sv + 128 + u);
                float v2 = __ldg(sv + 192 + u);
                atomicAdd(ag + u, wA * sA * y0);
                atomicAdd(ag + 64 + u, wD * (v0 * Y1 + v1 * Y2 + v2 * Y3) * inv_sqrt3);
                float bs = wB * sA;
                atomicAdd(ag + 128 + u, bs * Y1);
                atomicAdd(ag + 192 + u, bs * Y2);
                atomicAdd(ag + 256 + u, bs * Y3);
                float cy = wC * y0;
                atomicAdd(ag + 320 + u, cy * v0);
                atomicAdd(ag + 384 + u, cy * v1);
                atomicAdd(ag + 448 + u, cy * v2);
            }
        }
        __syncwarp();
    }
}

// ---------------- K4a: s_h = [agg_s | ns(x)attr] @ Wcat, gates + out_s ----------------
// smem: W 49152 + ops 384*16 = 55296 floats = 221184 B; 512 threads, 16 nodes/tile
#define K4A_SMEM 221184
__global__ void __launch_bounds__(512)
k4a(const float* __restrict__ ns, const float* __restrict__ attr,
    const float* __restrict__ Wl2s, const float* __restrict__ Wscs,
    float* __restrict__ out) {
    extern __shared__ float sm[];
    float* sW = sm;            // [384][128], pre-scaled
    float* sOp = sW + 49152;   // [384][16]
    int tid = threadIdx.x;
    const float lin2n = 0.08838834764831845f;  // 1/sqrt(128)
    const float scn = 0.0625f;                 // 1/sqrt(256)
    for (int i = tid; i < 16384; i += 512) sW[i] = Wl2s[i] * lin2n;
    for (int i = tid; i < 32768; i += 512) sW[16384 + i] = Wscs[i] * scn;
    __syncthreads();

    int w = tid & 127, nh = tid >> 7;  // nh 0..3, nodes nh*4..nh*4+3
    const int ntile = N_NODES / 16;    // 1250

    for (int tile = blockIdx.x; tile < ntile; tile += gridDim.x) {
        int n0 = tile * 16;
        {
            int k = tid & 127, q = tid >> 7;
#pragma unroll
            for (int nn = 0; nn < 4; nn++) {
                int node = q * 4 + nn;
                sOp[k * 16 + node] = g_agg[(size_t)(n0 + node) * 512 + k] * 0.0625f;
            }
            for (int idx = tid; idx < 4096; idx += 512) {
                int m = idx >> 4, node = idx & 15;
                sOp[(128 + m) * 16 + node] =
                    ns[(size_t)(n0 + node) * 64 + (m >> 2)] * attr[(size_t)(n0 + node) * 4 + (m & 3)];
            }
        }
        __syncthreads();

        u64t a01 = 0ull, a23 = 0ull;
#pragma unroll 4
        for (int k = 0; k < 384; k++) {
            u64t wd = pkdup(sW[k * 128 + w]);
            ulonglong2 op = *(const ulonglong2*)(sOp + k * 16 + nh * 4);
            fma2(a01, wd, op.x);
            fma2(a23, wd, op.y);
        }
        float2 r01 = up2(a01), r23 = up2(a23);
        float r[4] = {r01.x, r01.y, r23.x, r23.y};
#pragma unroll
        for (int j = 0; j < 4; j++) {
            int n = n0 + nh * 4 + j;
            float val = silu_n(r[j]);
            if (w < 64) out[(size_t)n * 256 + w] = val;
            else        g_gate[(size_t)n * 64 + (w - 64)] = val;
        }
        __syncthreads();
    }
}

// ---------------- K4b: v_h = [agg_v | nv(x)attr] @ Wvcat, gate + out_v ----------------
// smem: W 24576 + ops 384*8*4 = 36864 floats = 147456 B; 512 threads, 8 nodes/tile
#define K4B_SMEM 147456
__global__ void __launch_bounds__(512)
k4b(const float* __restrict__ nv, const float* __restrict__ attr,
    const float* __restrict__ Wl2v, const float* __restrict__ Wscv,
    float* __restrict__ out) {
    extern __shared__ float sm[];
    float* sW = sm;            // [384][64], pre-scaled
    float* sOp = sW + 24576;   // [384][8 nodes][4]
    int tid = threadIdx.x;
    const float lin2n = 0.08838834764831845f;
    const float scn = 0.0625f;
    for (int i = tid; i < 8192; i += 512)  sW[i] = Wl2v[i] * lin2n;
    for (int i = tid; i < 16384; i += 512) sW[8192 + i] = Wscv[i] * scn;
    __syncthreads();

    int w = tid & 63, node = tid >> 6;  // node 0..7
    const int ntile = N_NODES / 8;      // 2500

    for (int tile = blockIdx.x; tile < ntile; tile += gridDim.x) {
        int n0 = tile * 8;
        for (int idx = tid; idx < 3072; idx += 512) {
            int k = idx >> 3, nd = idx & 7;
            int n = n0 + nd;
            float o0, o1, o2;
            if (k < 128) {
                const float* p = g_agg + (size_t)n * 512 + ((k < 64) ? (128 + k) : (320 + k - 64));
                o0 = p[0] * 0.0625f; o1 = p[64] * 0.0625f; o2 = p[128] * 0.0625f;
            } else {
                int m = k - 128;
                int u = m >> 2, v = m & 3;
                float av = attr[(size_t)n * 4 + v];
                const float* p = nv + (size_t)n * 192 + u * 3;
                o0 = p[0] * av; o1 = p[1] * av; o2 = p[2] * av;
            }
            *(float4*)(sOp + idx * 4) = make_float4(o0, o1, o2, 0.f);
        }
        __syncthreads();

        u64t a01 = 0ull;
        float a2 = 0.f;
#pragma unroll 4
        for (int k = 0; k < 384; k++) {
            float wk = sW[k * 64 + w];
            u64t wd = pkdup(wk);
            ulonglong2 op = *(const ulonglong2*)(sOp + (k * 8 + node) * 4);
            fma2(a01, wd, op.x);
            float2 t = up2(op.y);
            a2 += wk * t.x;
        }
        int n = n0 + node;
        float gate = g_gate[(size_t)n * 64 + w];
        float2 r = up2(a01);
        float* o = out + (size_t)n * 256 + 64 + 3 * w;
        o[0] = gate * r.x; o[1] = gate * r.y; o[2] = gate * a2;
        __syncthreads();
    }
}

// ---------------- launch ----------------
extern "C" void kernel_launch(void* const* d_in, const int* in_sizes, int n_in,
                              void* d_out, int out_size) {
    const float* node_scalars  = (const float*)d_in[0];
    const float* node_vectors  = (const float*)d_in[1];
    const float* node_attr     = (const float*)d_in[2];
    const float* edge_sh       = (const float*)d_in[3];
    const float* edge_embedded = (const float*)d_in[4];
    const int*   edge_src      = (const int*)d_in[5];
    const int*   edge_dst      = (const int*)d_in[6];
    const float* W_lin1_s      = (const float*)d_in[7];
    const float* W_lin1_v      = (const float*)d_in[8];
    const float* W_fc0         = (const float*)d_in[9];
    const float* W_fc1         = (const float*)d_in[10];
    const float* W_fc2         = (const float*)d_in[11];
    const float* W_lin2_s      = (const float*)d_in[12];
    const float* W_lin2_v      = (const float*)d_in[13];
    const float* W_sc_s        = (const float*)d_in[14];
    const float* W_sc_v        = (const float*)d_in[15];
    float* out = (float*)d_out;

    cudaFuncSetAttribute(k3_edge, cudaFuncAttributeMaxDynamicSharedMemorySize, K3_SMEM);
    cudaFuncSetAttribute(k4a, cudaFuncAttributeMaxDynamicSharedMemorySize, K4A_SMEM);
    cudaFuncSetAttribute(k4b, cudaFuncAttributeMaxDynamicSharedMemorySize, K4B_SMEM);

    k1_lin1<<<N_NODES, 64>>>(node_scalars, node_vectors, W_lin1_s, W_lin1_v);
    k2_zero<<<1024, 256>>>();
    k3_edge<<<296, 256, K3_SMEM>>>(edge_sh, edge_embedded, edge_src, edge_dst,
                                   W_fc0, W_fc1, W_fc2);
    k4a<<<148, 512, K4A_SMEM>>>(node_scalars, node_attr, W_lin2_s, W_sc_s, out);
    k4b<<<148, 512, K4B_SMEM>>>(node_vectors, node_attr, W_lin2_v, W_sc_v, out);
}